// round 13
// baseline (speedup 1.0000x reference)
#include <cuda_runtime.h>
#include <cstdio>
#include <math.h>

// Canonical dims (confirmed via R5 diagnostic dump)
#define BLn  2048      // B*L
#define Ln   1024
#define Dn   256
#define Pn   32
#define CH   32        // chunk length (in l)
#define NCH  (BLn/CH)  // 64 chunks
#define CPB  (Ln/CH)   // 32 chunks per batch

#define MEMR ((long long)BLn * Pn * Dn)   // 16,777,216 f32 (real(memory))
#define PHN  ((long long)BLn * Pn)        // 65,536

// Scratch (__device__ globals; no allocation)
__device__ float g_values[BLn * Dn];      // 2 MB
__device__ float g_cos[BLn * Pn];         // 256 KB
__device__ float g_T[NCH * Pn * Dn];      // 2 MB  chunk totals (real)

// ---------------------------------------------------------------------------
// K1p: phase = tanh(x@Wp + bp)*pi ; cos(phase)
// One block per row; 256 threads = 8 k-groups x 32 p; smem tree reduce.
// ---------------------------------------------------------------------------
__global__ void __launch_bounds__(256) k1p_phase(
    const float* __restrict__ x,
    const float* __restrict__ Wp,   // [D, P]
    const float* __restrict__ bp,   // [P]
    float* __restrict__ out_phases,      // may be null
    float* __restrict__ out_phasors_re)  // may be null
{
    __shared__ float xr[Dn];
    __shared__ float part[8][Pn];
    const int row = blockIdx.x;
    const int tid = threadIdx.x;

    xr[tid] = x[(size_t)row * Dn + tid];
    __syncthreads();

    const int p = tid & 31, g = tid >> 5;
    const int k0 = g * 32;
    float s = 0.0f;
#pragma unroll
    for (int k = 0; k < 32; ++k)
        s = fmaf(xr[k0 + k], Wp[(k0 + k) * Pn + p], s);
    part[g][p] = s;
    __syncthreads();

    if (tid < Pn) {
        float pacc = bp[tid];
#pragma unroll
        for (int gg = 0; gg < 8; ++gg) pacc += part[gg][tid];
        const float phase = tanhf(pacc) * 3.14159274101257324f;
        const float c = cosf(phase);
        const size_t idx = (size_t)row * Pn + tid;
        g_cos[idx] = c;
        if (out_phases)     out_phases[idx]     = phase;
        if (out_phasors_re) out_phasors_re[idx] = c;
    }
}

// ---------------------------------------------------------------------------
// K1v: values = x@Wv + bv
// 8 rows/block -> 256 blocks; block dim3(64,4); thread = 2 rows x 4 cols.
// ---------------------------------------------------------------------------
__global__ void __launch_bounds__(256) k1v_values(
    const float* __restrict__ x,
    const float* __restrict__ Wv,   // [D, D]
    const float* __restrict__ bv)   // [D]
{
    __shared__ float xs[8][Dn];     // 8 KB
    const int tx  = threadIdx.x;    // 0..63 -> float4 col group
    const int ty  = threadIdx.y;    // 0..3
    const int tid = ty * 64 + tx;
    const int row0 = blockIdx.x * 8;

    for (int i = tid; i < 8 * Dn; i += 256)
        xs[i >> 8][i & (Dn - 1)] = x[(size_t)row0 * Dn + i];
    __syncthreads();

    const float4 bvv = reinterpret_cast<const float4*>(bv)[tx];
    float4 a0 = bvv, a1 = bvv;

    const float4* Wv4 = reinterpret_cast<const float4*>(Wv);
#pragma unroll 8
    for (int k = 0; k < Dn; ++k) {
        const float4 w  = Wv4[k * 64 + tx];
        const float  x0 = xs[ty][k];
        const float  x1 = xs[ty + 4][k];
        a0.x = fmaf(x0, w.x, a0.x);
        a0.y = fmaf(x0, w.y, a0.y);
        a0.z = fmaf(x0, w.z, a0.z);
        a0.w = fmaf(x0, w.w, a0.w);
        a1.x = fmaf(x1, w.x, a1.x);
        a1.y = fmaf(x1, w.y, a1.y);
        a1.z = fmaf(x1, w.z, a1.z);
        a1.w = fmaf(x1, w.w, a1.w);
    }
    reinterpret_cast<float4*>(g_values)[(size_t)(row0 + ty) * 64 + tx]     = a0;
    reinterpret_cast<float4*>(g_values)[(size_t)(row0 + ty + 4) * 64 + tx] = a1;
}

// ---------------------------------------------------------------------------
// K2: chunk totals T[ch][p][d] = sum_{l in ch} cos[l][p] * value[l][d]
// grid NCH=64 blocks, 256 threads (one d each), 32 p-accumulators per thread
// ---------------------------------------------------------------------------
__global__ void __launch_bounds__(256) k2_chunktotals()
{
    __shared__ float cs[CH][Pn];   // 4 KB
    const int ch  = blockIdx.x;
    const int d   = threadIdx.x;
    const int lb  = ch * CH;

    for (int i = threadIdx.x; i < CH * Pn; i += 256)
        cs[i >> 5][i & 31] = g_cos[(size_t)lb * Pn + i];
    __syncthreads();

    float acc[Pn];
#pragma unroll
    for (int p = 0; p < Pn; ++p) acc[p] = 0.0f;

#pragma unroll 2
    for (int l = 0; l < CH; ++l) {
        const float v = g_values[(size_t)(lb + l) * Dn + d];
#pragma unroll
        for (int q = 0; q < Pn / 4; ++q) {
            const float4 c4 = *reinterpret_cast<const float4*>(&cs[l][q * 4]);
            acc[q * 4 + 0] = fmaf(c4.x, v, acc[q * 4 + 0]);
            acc[q * 4 + 1] = fmaf(c4.y, v, acc[q * 4 + 1]);
            acc[q * 4 + 2] = fmaf(c4.z, v, acc[q * 4 + 2]);
            acc[q * 4 + 3] = fmaf(c4.w, v, acc[q * 4 + 3]);
        }
    }
#pragma unroll
    for (int p = 0; p < Pn; ++p)
        g_T[((size_t)ch * Pn + p) * Dn + d] = acc[p];
}

// ---------------------------------------------------------------------------
// K3: scan within one chunk, p tiled inside the block; seed computed
// IN-KERNEL from preceding chunk totals (front-batched float4 loads).
// grid = NCH * 4 d-quarters = 256 blocks; 256 threads = 16 p-lanes x 16 d4.
// ---------------------------------------------------------------------------
__global__ void __launch_bounds__(256) k3_scan(float* __restrict__ out)
{
    __shared__ float4 vs[CH][16];   // 8 KB: value sub-tile (32 l x 64 d)
    __shared__ float  cs[CH][Pn];   // 4 KB: cos tile (32 l x 32 p)

    const int ch = blockIdx.x >> 2;
    const int dq = blockIdx.x & 3;
    const int lb = ch * CH;
    const int t  = threadIdx.x;
    const int dg = t & 15;          // float4 group within quarter
    const int pl = t >> 4;          // 0..15 p-lane
    const int d4 = dq * 16 + dg;    // global float4-of-d index (0..63)

    // stage values sub-tile: 512 float4 by 256 threads (2 each)
    {
        const float4* v4 = reinterpret_cast<const float4*>(g_values);
#pragma unroll
        for (int r = 0; r < 2; ++r) {
            const int i = t + r * 256;     // 0..511
            const int l = i >> 4, g = i & 15;
            vs[l][g] = v4[(size_t)(lb + l) * 64 + dq * 16 + g];
        }
    }
    // stage cos tile: 1024 floats by 256 threads (4 each)
    for (int i = t; i < CH * Pn; i += 256)
        cs[i >> 5][i & 31] = g_cos[(size_t)lb * Pn + i];
    __syncthreads();

    const float4* T4 = reinterpret_cast<const float4*>(g_T);
    float4* out4 = reinterpret_cast<float4*>(out);

    const int ch0 = (ch >> 5) << 5;   // first chunk of this batch (CPB = 32)

#pragma unroll
    for (int pi = 0; pi < 2; ++pi) {
        const int p = pl + pi * 16;

        // seed = exclusive prefix over chunks [ch0, ch); independent loads
        float4 re = make_float4(0.f, 0.f, 0.f, 0.f);
#pragma unroll 8
        for (int c = ch0; c < ch; ++c) {
            const float4 tv = T4[((size_t)c * Pn + p) * 64 + d4];
            re.x += tv.x;
            re.y += tv.y;
            re.z += tv.z;
            re.w += tv.w;
        }

#pragma unroll
        for (int l = 0; l < CH; ++l) {
            const float  c = cs[l][p];
            const float4 v = vs[l][dg];
            re.x = fmaf(c, v.x, re.x);
            re.y = fmaf(c, v.y, re.y);
            re.z = fmaf(c, v.z, re.z);
            re.w = fmaf(c, v.w, re.w);
            out4[((size_t)(lb + l) * Pn + p) * 64 + d4] = re;
        }
    }
}

// ---------------------------------------------------------------------------
extern "C" void kernel_launch(void* const* d_in, const int* in_sizes, int n_in,
                              void* d_out, int out_size)
{
    // Verify canonical contract (confirmed by R5 dump, dict order)
    if (n_in < 5 ||
        in_sizes[0] != BLn * Dn || in_sizes[1] != Dn * Pn ||
        in_sizes[2] != Pn       || in_sizes[3] != Dn * Dn ||
        in_sizes[4] != Dn) {
        fprintf(stderr, "[klaunch] BAIL: unexpected input sizes\n");
        return;
    }
    const float* x  = (const float*)d_in[0];
    const float* Wp = (const float*)d_in[1];
    const float* bp = (const float*)d_in[2];
    const float* Wv = (const float*)d_in[3];
    const float* bv = (const float*)d_in[4];

    float* out = (float*)d_out;
    const long long n = out_size;

    // Real-part layout: real(mem) [MEMR] | phases [PHN] | real(phasors) [PHN]
    if (n < MEMR) {
        fprintf(stderr, "[klaunch] BAIL: out_size=%lld < MEMR=%lld\n", n, MEMR);
        return;
    }
    const int has_aux = (n >= MEMR + 2 * PHN);
    float* out_phases     = has_aux ? (out + MEMR)       : nullptr;
    float* out_phasors_re = has_aux ? (out + MEMR + PHN) : nullptr;

    k1p_phase<<<BLn, 256>>>(x, Wp, bp, out_phases, out_phasors_re);
    k1v_values<<<BLn / 8, dim3(64, 4)>>>(x, Wv, bv);
    k2_chunktotals<<<NCH, 256>>>();
    k3_scan<<<NCH * 4, 256>>>(out);
}

// round 14
// speedup vs baseline: 1.0887x; 1.0887x over previous
#include <cuda_runtime.h>
#include <cstdio>
#include <math.h>

// Canonical dims (confirmed via R5 diagnostic dump)
#define BLn  2048      // B*L
#define Ln   1024
#define Dn   256
#define Pn   32
#define CH   32        // chunk length (in l)
#define NCH  (BLn/CH)  // 64 chunks
#define CPB  (Ln/CH)   // 32 chunks per batch

#define MEMR ((long long)BLn * Pn * Dn)   // 16,777,216 f32 (real(memory))
#define PHN  ((long long)BLn * Pn)        // 65,536

// Scratch (__device__ globals; no allocation)
__device__ float g_values[BLn * Dn];      // 2 MB
__device__ float g_cos[BLn * Pn];         // 256 KB
__device__ float g_T[NCH * Pn * Dn];      // 2 MB  chunk totals (real)
__device__ float g_Tpre[NCH * Pn * Dn];   // 2 MB  exclusive chunk prefixes

// ---------------------------------------------------------------------------
// K1p: phase = tanh(x@Wp + bp)*pi ; cos(phase)
// One block per row; 256 threads = 8 k-groups x 32 p; smem tree reduce.
// ---------------------------------------------------------------------------
__global__ void __launch_bounds__(256) k1p_phase(
    const float* __restrict__ x,
    const float* __restrict__ Wp,   // [D, P]
    const float* __restrict__ bp,   // [P]
    float* __restrict__ out_phases,      // may be null
    float* __restrict__ out_phasors_re)  // may be null
{
    __shared__ float xr[Dn];
    __shared__ float part[8][Pn];
    const int row = blockIdx.x;
    const int tid = threadIdx.x;

    xr[tid] = x[(size_t)row * Dn + tid];
    __syncthreads();

    const int p = tid & 31, g = tid >> 5;
    const int k0 = g * 32;
    float s = 0.0f;
#pragma unroll
    for (int k = 0; k < 32; ++k)
        s = fmaf(xr[k0 + k], Wp[(k0 + k) * Pn + p], s);
    part[g][p] = s;
    __syncthreads();

    if (tid < Pn) {
        float pacc = bp[tid];
#pragma unroll
        for (int gg = 0; gg < 8; ++gg) pacc += part[gg][tid];
        const float phase = tanhf(pacc) * 3.14159274101257324f;
        const float c = cosf(phase);
        const size_t idx = (size_t)row * Pn + tid;
        g_cos[idx] = c;
        if (out_phases)     out_phases[idx]     = phase;
        if (out_phasors_re) out_phasors_re[idx] = c;
    }
}

// ---------------------------------------------------------------------------
// K1v: values = x@Wv + bv
// 8 rows/block -> 256 blocks; block dim3(64,4); thread = 2 rows x 4 cols.
// ---------------------------------------------------------------------------
__global__ void __launch_bounds__(256) k1v_values(
    const float* __restrict__ x,
    const float* __restrict__ Wv,   // [D, D]
    const float* __restrict__ bv)   // [D]
{
    __shared__ float xs[8][Dn];     // 8 KB
    const int tx  = threadIdx.x;    // 0..63 -> float4 col group
    const int ty  = threadIdx.y;    // 0..3
    const int tid = ty * 64 + tx;
    const int row0 = blockIdx.x * 8;

    for (int i = tid; i < 8 * Dn; i += 256)
        xs[i >> 8][i & (Dn - 1)] = x[(size_t)row0 * Dn + i];
    __syncthreads();

    const float4 bvv = reinterpret_cast<const float4*>(bv)[tx];
    float4 a0 = bvv, a1 = bvv;

    const float4* Wv4 = reinterpret_cast<const float4*>(Wv);
#pragma unroll 8
    for (int k = 0; k < Dn; ++k) {
        const float4 w  = Wv4[k * 64 + tx];
        const float  x0 = xs[ty][k];
        const float  x1 = xs[ty + 4][k];
        a0.x = fmaf(x0, w.x, a0.x);
        a0.y = fmaf(x0, w.y, a0.y);
        a0.z = fmaf(x0, w.z, a0.z);
        a0.w = fmaf(x0, w.w, a0.w);
        a1.x = fmaf(x1, w.x, a1.x);
        a1.y = fmaf(x1, w.y, a1.y);
        a1.z = fmaf(x1, w.z, a1.z);
        a1.w = fmaf(x1, w.w, a1.w);
    }
    reinterpret_cast<float4*>(g_values)[(size_t)(row0 + ty) * 64 + tx]     = a0;
    reinterpret_cast<float4*>(g_values)[(size_t)(row0 + ty + 4) * 64 + tx] = a1;
}

// ---------------------------------------------------------------------------
// K2: chunk totals T[ch][p][d] = sum_{l in ch} cos[l][p] * value[l][d]
// grid NCH=64 blocks, 256 threads (one d each), 32 p-accumulators per thread
// ---------------------------------------------------------------------------
__global__ void __launch_bounds__(256) k2_chunktotals()
{
    __shared__ float cs[CH][Pn];   // 4 KB
    const int ch  = blockIdx.x;
    const int d   = threadIdx.x;
    const int lb  = ch * CH;

    for (int i = threadIdx.x; i < CH * Pn; i += 256)
        cs[i >> 5][i & 31] = g_cos[(size_t)lb * Pn + i];
    __syncthreads();

    float acc[Pn];
#pragma unroll
    for (int p = 0; p < Pn; ++p) acc[p] = 0.0f;

#pragma unroll 2
    for (int l = 0; l < CH; ++l) {
        const float v = g_values[(size_t)(lb + l) * Dn + d];
#pragma unroll
        for (int q = 0; q < Pn / 4; ++q) {
            const float4 c4 = *reinterpret_cast<const float4*>(&cs[l][q * 4]);
            acc[q * 4 + 0] = fmaf(c4.x, v, acc[q * 4 + 0]);
            acc[q * 4 + 1] = fmaf(c4.y, v, acc[q * 4 + 1]);
            acc[q * 4 + 2] = fmaf(c4.z, v, acc[q * 4 + 2]);
            acc[q * 4 + 3] = fmaf(c4.w, v, acc[q * 4 + 3]);
        }
    }
#pragma unroll
    for (int p = 0; p < Pn; ++p)
        g_T[((size_t)ch * Pn + p) * Dn + d] = acc[p];
}

// ---------------------------------------------------------------------------
// K2b: exclusive prefix over the 32 chunks of each batch.
// grid = 2 batches * 32 p = 64 blocks, 64 threads (thread owns float4 of d).
// All 32 loads issued up front (high MLP), prefix in regs, 32 stores.
// ---------------------------------------------------------------------------
__global__ void __launch_bounds__(64) k2b_prefix()
{
    const int p     = blockIdx.x & 31;
    const int batch = blockIdx.x >> 5;
    const int ch0   = batch * CPB;
    const int t     = threadIdx.x;          // 0..63 float4 groups of d

    const float4* T4   = reinterpret_cast<const float4*>(g_T);
    float4*       Tp4  = reinterpret_cast<float4*>(g_Tpre);
    const size_t  base = ((size_t)ch0 * Pn + p) * (Dn / 4) + t;
    const size_t  str  = (size_t)Pn * (Dn / 4);

    float4 v[CPB];
#pragma unroll
    for (int c = 0; c < CPB; ++c)
        v[c] = T4[base + (size_t)c * str];

    float4 run = make_float4(0.f, 0.f, 0.f, 0.f);
#pragma unroll
    for (int c = 0; c < CPB; ++c) {
        const float4 cur = v[c];
        Tp4[base + (size_t)c * str] = run;
        run.x += cur.x;
        run.y += cur.y;
        run.z += cur.z;
        run.w += cur.w;
    }
}

// ---------------------------------------------------------------------------
// K3: scan within one chunk, p tiled inside the block (values read once per
// p-half). grid = NCH * 4 dq * 2 ph = 512 blocks; 256 threads = 16 pl x 16 dg.
// Each block: 16 p x 64 d; single p iteration -> lower regs, higher occ.
// ---------------------------------------------------------------------------
__global__ void __launch_bounds__(256) k3_scan(float* __restrict__ out)
{
    __shared__ float4 vs[CH][16];   // 8 KB: value sub-tile (32 l x 64 d)
    __shared__ float  cs[CH][16];   // 2 KB: cos tile (32 l x 16 p)

    const int ch = blockIdx.x >> 3;
    const int dq = (blockIdx.x >> 1) & 3;
    const int ph = blockIdx.x & 1;
    const int lb = ch * CH;
    const int t  = threadIdx.x;
    const int dg = t & 15;          // float4 group within quarter
    const int pl = t >> 4;          // 0..15 p-lane
    const int p  = ph * 16 + pl;
    const int d4 = dq * 16 + dg;    // global float4-of-d index (0..63)

    // stage values sub-tile: 512 float4 by 256 threads (2 each)
    {
        const float4* v4 = reinterpret_cast<const float4*>(g_values);
#pragma unroll
        for (int r = 0; r < 2; ++r) {
            const int i = t + r * 256;     // 0..511
            const int l = i >> 4, g = i & 15;
            vs[l][g] = v4[(size_t)(lb + l) * 64 + dq * 16 + g];
        }
    }
    // stage cos half-tile: 512 floats by 256 threads (2 each)
#pragma unroll
    for (int r = 0; r < 2; ++r) {
        const int i = t + r * 256;         // 0..511
        const int l = i >> 4, pp = i & 15;
        cs[l][pp] = g_cos[(size_t)(lb + l) * Pn + ph * 16 + pp];
    }
    __syncthreads();

    const float4* Tp4 = reinterpret_cast<const float4*>(g_Tpre);
    float4* out4 = reinterpret_cast<float4*>(out);

    float4 re = Tp4[((size_t)ch * Pn + p) * 64 + d4];
#pragma unroll
    for (int l = 0; l < CH; ++l) {
        const float  c = cs[l][pl];
        const float4 v = vs[l][dg];
        re.x = fmaf(c, v.x, re.x);
        re.y = fmaf(c, v.y, re.y);
        re.z = fmaf(c, v.z, re.z);
        re.w = fmaf(c, v.w, re.w);
        out4[((size_t)(lb + l) * Pn + p) * 64 + d4] = re;
    }
}

// ---------------------------------------------------------------------------
extern "C" void kernel_launch(void* const* d_in, const int* in_sizes, int n_in,
                              void* d_out, int out_size)
{
    // Verify canonical contract (confirmed by R5 dump, dict order)
    if (n_in < 5 ||
        in_sizes[0] != BLn * Dn || in_sizes[1] != Dn * Pn ||
        in_sizes[2] != Pn       || in_sizes[3] != Dn * Dn ||
        in_sizes[4] != Dn) {
        fprintf(stderr, "[klaunch] BAIL: unexpected input sizes\n");
        return;
    }
    const float* x  = (const float*)d_in[0];
    const float* Wp = (const float*)d_in[1];
    const float* bp = (const float*)d_in[2];
    const float* Wv = (const float*)d_in[3];
    const float* bv = (const float*)d_in[4];

    float* out = (float*)d_out;
    const long long n = out_size;

    // Real-part layout: real(mem) [MEMR] | phases [PHN] | real(phasors) [PHN]
    if (n < MEMR) {
        fprintf(stderr, "[klaunch] BAIL: out_size=%lld < MEMR=%lld\n", n, MEMR);
        return;
    }
    const int has_aux = (n >= MEMR + 2 * PHN);
    float* out_phases     = has_aux ? (out + MEMR)       : nullptr;
    float* out_phasors_re = has_aux ? (out + MEMR + PHN) : nullptr;

    k1p_phase<<<BLn, 256>>>(x, Wp, bp, out_phases, out_phasors_re);
    k1v_values<<<BLn / 8, dim3(64, 4)>>>(x, Wv, bv);
    k2_chunktotals<<<NCH, 256>>>();
    k2b_prefix<<<2 * Pn, 64>>>();
    k3_scan<<<NCH * 8, 256>>>(out);
}